// round 16
// baseline (speedup 1.0000x reference)
#include <cuda_runtime.h>
#include <cuda_bf16.h>
#include <cstdint>
#include <cstddef>
#include <math.h>

#define MROWS 4096           // B*S
#define EDIM  1024
#define SLEN  2048
#define NHEAD 8

// ---------------- warp-level bf16 MMA (m16n8k16, fp32 accum) ----------------
__device__ __forceinline__ void mma16816(
    float* c, const unsigned* a, const unsigned* b)
{
    asm volatile(
        "mma.sync.aligned.m16n8k16.row.col.f32.bf16.bf16.f32 "
        "{%0,%1,%2,%3}, {%4,%5,%6,%7}, {%8,%9}, {%0,%1,%2,%3};"
        : "+f"(c[0]), "+f"(c[1]), "+f"(c[2]), "+f"(c[3])
        : "r"(a[0]), "r"(a[1]), "r"(a[2]), "r"(a[3]), "r"(b[0]), "r"(b[1]));
}
__device__ __forceinline__ void ldsm4(unsigned* r, unsigned addr) {
    asm volatile("ldmatrix.sync.aligned.m8n8.x4.shared.b16 {%0,%1,%2,%3}, [%4];"
        : "=r"(r[0]), "=r"(r[1]), "=r"(r[2]), "=r"(r[3]) : "r"(addr));
}
__device__ __forceinline__ void ldsm4t(unsigned* r, unsigned addr) {
    asm volatile("ldmatrix.sync.aligned.m8n8.x4.trans.shared.b16 {%0,%1,%2,%3}, [%4];"
        : "=r"(r[0]), "=r"(r[1]), "=r"(r[2]), "=r"(r[3]) : "r"(addr));
}
__device__ __forceinline__ unsigned smem_to_u32(const void* p) {
    unsigned a;
    asm("{ .reg .u64 t; cvta.to.shared.u64 t, %1; cvt.u32.u64 %0, t; }" : "=r"(a) : "l"(p));
    return a;
}
// pack two fp32 into bf16x2: low half = lo, high half = hi
__device__ __forceinline__ unsigned cvt2(float hi, float lo) {
    unsigned r; asm("cvt.rn.bf16x2.f32 %0, %1, %2;" : "=r"(r) : "f"(hi), "f"(lo));
    return r;
}
__device__ __forceinline__ float ex2f(float x) {
    float r; asm("ex2.approx.f32 %0, %1;" : "=f"(r) : "f"(x)); return r;
}
#define CP_ASYNC16(dst_u32, src) \
    asm volatile("cp.async.cg.shared.global [%0], [%1], 16;" :: "r"(dst_u32), "l"(src))
#define CP_COMMIT() asm volatile("cp.async.commit_group;" ::: "memory")
#define CP_WAIT0()  asm volatile("cp.async.wait_group 0;" ::: "memory")
#define CP_WAIT1()  asm volatile("cp.async.wait_group 1;" ::: "memory")

// ---------------- scratch (device globals: allocation-free) ----------------
__device__ float g_o[(size_t)MROWS * EDIM];
__device__ __nv_bfloat16 g_xhi[(size_t)MROWS * EDIM];
__device__ __nv_bfloat16 g_xlo[(size_t)MROWS * EDIM];
__device__ __nv_bfloat16 g_nhi[(size_t)MROWS * EDIM];
__device__ __nv_bfloat16 g_nlo[(size_t)MROWS * EDIM];
__device__ __nv_bfloat16 g_qh[(size_t)MROWS * EDIM];
__device__ __nv_bfloat16 g_ql[(size_t)MROWS * EDIM];
__device__ __nv_bfloat16 g_kh[(size_t)MROWS * EDIM];
__device__ __nv_bfloat16 g_kl[(size_t)MROWS * EDIM];
__device__ __nv_bfloat16 g_vh[(size_t)MROWS * EDIM];
__device__ __nv_bfloat16 g_vl[(size_t)MROWS * EDIM];
__device__ __nv_bfloat16 g_wqhi[(size_t)EDIM * EDIM];
__device__ __nv_bfloat16 g_wqlo[(size_t)EDIM * EDIM];
__device__ __nv_bfloat16 g_wkhi[(size_t)EDIM * EDIM];
__device__ __nv_bfloat16 g_wklo[(size_t)EDIM * EDIM];
__device__ __nv_bfloat16 g_wvhi[(size_t)EDIM * EDIM];
__device__ __nv_bfloat16 g_wvlo[(size_t)EDIM * EDIM];
__device__ __nv_bfloat16 g_wohi[(size_t)EDIM * EDIM];
__device__ __nv_bfloat16 g_wolo[(size_t)EDIM * EDIM];

struct QKVPtrs {
    const __nv_bfloat16* Bh[3];
    const __nv_bfloat16* Bl[3];
    __nv_bfloat16* Ch[3];
    __nv_bfloat16* Cl[3];
    float cscale[3];
};
struct SplitPtrs {
    const float* src[4];
    __nv_bfloat16* hi[4];
    __nv_bfloat16* lo[4];
};

// ======================================================================
// fp32 -> (bf16 hi, bf16 lo) split, vectorized float4
// ======================================================================
__global__ void __launch_bounds__(256) split_bf16_kernel(
    const float* __restrict__ x, __nv_bfloat16* __restrict__ hi,
    __nv_bfloat16* __restrict__ lo, int n4)
{
    int i = blockIdx.x * 256 + threadIdx.x;
    if (i >= n4) return;
    float4 v = ((const float4*)x)[i];
    float vv[4] = { v.x, v.y, v.z, v.w };
    __nv_bfloat16 h[4], l[4];
#pragma unroll
    for (int j = 0; j < 4; j++) {
        h[j] = __float2bfloat16_rn(vv[j]);
        l[j] = __float2bfloat16_rn(vv[j] - __bfloat162float(h[j]));
    }
    __nv_bfloat162* hp = (__nv_bfloat162*)hi;
    __nv_bfloat162* lp = (__nv_bfloat162*)lo;
    hp[i * 2 + 0] = __nv_bfloat162(h[0], h[1]);
    hp[i * 2 + 1] = __nv_bfloat162(h[2], h[3]);
    lp[i * 2 + 0] = __nv_bfloat162(l[0], l[1]);
    lp[i * 2 + 1] = __nv_bfloat162(l[2], l[3]);
}

// fused 4-weight split: blockIdx.y selects the weight matrix
__global__ void __launch_bounds__(256) split_bf16_multi_kernel(SplitPtrs p, int n4)
{
    int i = blockIdx.x * 256 + threadIdx.x;
    if (i >= n4) return;
    const int w = blockIdx.y;
    float4 v = ((const float4*)p.src[w])[i];
    float vv[4] = { v.x, v.y, v.z, v.w };
    __nv_bfloat16 h[4], l[4];
#pragma unroll
    for (int j = 0; j < 4; j++) {
        h[j] = __float2bfloat16_rn(vv[j]);
        l[j] = __float2bfloat16_rn(vv[j] - __bfloat162float(h[j]));
    }
    __nv_bfloat162* hp = (__nv_bfloat162*)p.hi[w];
    __nv_bfloat162* lp = (__nv_bfloat162*)p.lo[w];
    hp[i * 2 + 0] = __nv_bfloat162(h[0], h[1]);
    hp[i * 2 + 1] = __nv_bfloat162(h[2], h[3]);
    lp[i * 2 + 0] = __nv_bfloat162(l[0], l[1]);
    lp[i * 2 + 1] = __nv_bfloat162(l[2], l[3]);
}

// ======================================================================
// HMMA split-bf16 GEMM, BK=32, cp.async double-buffered, dynamic smem.
// MMA issue interleaved across the 4 n-tiles (dependency distance 4).
// ======================================================================
#define GTS   40                    // bf16 row stride (80 B)
#define GTILE (128 * GTS * 2)       // 10240 bytes per tile
#define GBUF  (4 * GTILE)           // 40960 bytes per buffer (Ah, Al, Bh, Bl)
#define GSMEM_BYTES (2 * GBUF)      // 81920

__global__ void __launch_bounds__(256, 2) mma_gemm_kernel(
    const __nv_bfloat16* __restrict__ Ahi, const __nv_bfloat16* __restrict__ Alo,
    QKVPtrs p, float* __restrict__ Cf,
    const float* __restrict__ bias, const float* __restrict__ dwp)
{
    extern __shared__ char gsm[];
    const unsigned su = smem_to_u32(gsm);

    const int tid = threadIdx.x;
    const int wid = tid >> 5, L = tid & 31;
    const int sel = blockIdx.x >> 3;
    const int bm = blockIdx.y * 128, bn = (blockIdx.x & 7) * 128;
    const int wm = (wid >> 2) * 64, wn = (wid & 3) * 32;
    const __nv_bfloat16* __restrict__ Bhi = p.Bh[sel];
    const __nv_bfloat16* __restrict__ Blo = p.Bl[sel];

    const int lrow = tid >> 1;                 // 0..127
    const int lcol = (tid & 1) * 16;           // bf16 offset within 32
    const unsigned soff = (unsigned)(lrow * 80 + (tid & 1) * 32);

    const int fr = L >> 2, fc = (L & 3) * 2;
    const int lm = L >> 3, lr = L & 7;
    const unsigned offA = (unsigned)((lr + ((lm & 1) << 3)) * 80 + ((lm >> 1) << 4));
    const unsigned offB = (unsigned)((lr + ((lm >> 1) << 3)) * 80 + ((lm & 1) << 4));

    float acc[4][4][4];
#pragma unroll
    for (int mt = 0; mt < 4; mt++)
#pragma unroll
        for (int nt = 0; nt < 4; nt++)
#pragma unroll
            for (int e = 0; e < 4; e++) acc[mt][nt][e] = 0.f;

    const int K = EDIM;
    const int nchunks = K / 32;   // 32

    {
        const unsigned base = su;
        const size_t arow = (size_t)(bm + lrow) * K + lcol;
        const size_t brow = (size_t)(bn + lrow) * K + lcol;
        CP_ASYNC16(base + 0 * GTILE + soff,      Ahi + arow);
        CP_ASYNC16(base + 0 * GTILE + soff + 16, Ahi + arow + 8);
        CP_ASYNC16(base + 1 * GTILE + soff,      Alo + arow);
        CP_ASYNC16(base + 1 * GTILE + soff + 16, Alo + arow + 8);
        CP_ASYNC16(base + 2 * GTILE + soff,      Bhi + brow);
        CP_ASYNC16(base + 2 * GTILE + soff + 16, Bhi + brow + 8);
        CP_ASYNC16(base + 3 * GTILE + soff,      Blo + brow);
        CP_ASYNC16(base + 3 * GTILE + soff + 16, Blo + brow + 8);
        CP_COMMIT();
    }

    for (int c = 0; c < nchunks; c++) {
        CP_WAIT0();
        __syncthreads();
        const unsigned base = su + (unsigned)((c & 1) * GBUF);
        if (c + 1 < nchunks) {
            const unsigned nbase = su + (unsigned)(((c + 1) & 1) * GBUF);
            const size_t arow = (size_t)(bm + lrow) * K + (c + 1) * 32 + lcol;
            const size_t brow = (size_t)(bn + lrow) * K + (c + 1) * 32 + lcol;
            CP_ASYNC16(nbase + 0 * GTILE + soff,      Ahi + arow);
            CP_ASYNC16(nbase + 0 * GTILE + soff + 16, Ahi + arow + 8);
            CP_ASYNC16(nbase + 1 * GTILE + soff,      Alo + arow);
            CP_ASYNC16(nbase + 1 * GTILE + soff + 16, Alo + arow + 8);
            CP_ASYNC16(nbase + 2 * GTILE + soff,      Bhi + brow);
            CP_ASYNC16(nbase + 2 * GTILE + soff + 16, Bhi + brow + 8);
            CP_ASYNC16(nbase + 3 * GTILE + soff,      Blo + brow);
            CP_ASYNC16(nbase + 3 * GTILE + soff + 16, Blo + brow + 8);
            CP_COMMIT();
        }

#pragma unroll
        for (int ks = 0; ks < 2; ks++) {
            const unsigned koff = (unsigned)(ks * 32);
            unsigned bh[4][2], bl[4][2];
#pragma unroll
            for (int ntp = 0; ntp < 2; ntp++) {
                unsigned t[4];
                ldsm4(t, base + 2 * GTILE + (wn + ntp * 16) * 80 + koff + offB);
                bh[2 * ntp][0] = t[0]; bh[2 * ntp][1] = t[1];
                bh[2 * ntp + 1][0] = t[2]; bh[2 * ntp + 1][1] = t[3];
                ldsm4(t, base + 3 * GTILE + (wn + ntp * 16) * 80 + koff + offB);
                bl[2 * ntp][0] = t[0]; bl[2 * ntp][1] = t[1];
                bl[2 * ntp + 1][0] = t[2]; bl[2 * ntp + 1][1] = t[3];
            }
#pragma unroll
            for (int mt = 0; mt < 4; mt++) {
                unsigned ah[4], al[4];
                ldsm4(ah, base + 0 * GTILE + (wm + mt * 16) * 80 + koff + offA);
                ldsm4(al, base + 1 * GTILE + (wm + mt * 16) * 80 + koff + offA);
                // term-major: 4 independent chains per term
#pragma unroll
                for (int nt = 0; nt < 4; nt++) mma16816(acc[mt][nt], ah, bh[nt]);
#pragma unroll
                for (int nt = 0; nt < 4; nt++) mma16816(acc[mt][nt], ah, bl[nt]);
#pragma unroll
                for (int nt = 0; nt < 4; nt++) mma16816(acc[mt][nt], al, bh[nt]);
            }
        }
    }

    if (Cf) {
        float sc = 1.0f;
        if (dwp) sc = 1.0f - *dwp;
#pragma unroll
        for (int mt = 0; mt < 4; mt++) {
#pragma unroll
            for (int nt = 0; nt < 4; nt++) {
                int row = bm + wm + mt * 16 + fr;
                int col = bn + wn + nt * 8 + fc;
                float b0 = 0.f, b1 = 0.f;
                if (bias) { b0 = bias[col]; b1 = bias[col + 1]; }
                float2 r0, r1;
                r0.x = (acc[mt][nt][0] + b0) * sc;
                r0.y = (acc[mt][nt][1] + b1) * sc;
                r1.x = (acc[mt][nt][2] + b0) * sc;
                r1.y = (acc[mt][nt][3] + b1) * sc;
                *(float2*)(Cf + (size_t)row * EDIM + col) = r0;
                *(float2*)(Cf + (size_t)(row + 8) * EDIM + col) = r1;
            }
        }
    } else {
        __nv_bfloat16* __restrict__ Chi = p.Ch[sel];
        __nv_bfloat16* __restrict__ Clo = p.Cl[sel];
        const float cs = p.cscale[sel];
#pragma unroll
        for (int mt = 0; mt < 4; mt++) {
#pragma unroll
            for (int nt = 0; nt < 4; nt++) {
                int row = bm + wm + mt * 16 + fr;
                int col = bn + wn + nt * 8 + fc;
#pragma unroll
                for (int half = 0; half < 2; half++) {
                    float v0 = acc[mt][nt][half * 2 + 0] * cs;
                    float v1 = acc[mt][nt][half * 2 + 1] * cs;
                    __nv_bfloat16 h0 = __float2bfloat16_rn(v0);
                    __nv_bfloat16 h1 = __float2bfloat16_rn(v1);
                    __nv_bfloat16 l0 = __float2bfloat16_rn(v0 - __bfloat162float(h0));
                    __nv_bfloat16 l1 = __float2bfloat16_rn(v1 - __bfloat162float(h1));
                    size_t off = (size_t)(row + half * 8) * EDIM + col;
                    *(__nv_bfloat162*)(Chi + off) = __nv_bfloat162(h0, h1);
                    *(__nv_bfloat162*)(Clo + off) = __nv_bfloat162(l0, l1);
                }
            }
        }
    }
}

// ======================================================================
// HMMA differential flash attention, BQ=128, no-max softmax (ex2),
// MMA issue interleaved across 4 accumulator chains, double-buffered K/V.
// q projection pre-scaled by 0.125*log2e, so p = ex2(s).
// CTA: (b, h, 128-q tile), 8 warps. Warps 0-3: branch0, 4-7: branch1.
// ======================================================================
#define BQ 128
#define BKT 64
#define QB  272   // byte stride for Q/K/V bf16 tiles (136 bf16)
#define OSR 132   // fp32 stride for O staging

#define OFF_QHI  0
#define OFF_QLO  34816
#define OFF_KV   69632       // 2 buffers x 4 tiles x 17408 bytes
#define KV_BUF   69632       // bytes per buffer set
#define KV_KHI   0
#define KV_KLO   17408
#define KV_VHI   34816
#define KV_VLO   52224
#define ATT_SMEM_BYTES (OFF_KV + 2 * KV_BUF)   // 208896

__global__ void __launch_bounds__(256) diff_attn_mma_kernel(
    const __nv_bfloat16* __restrict__ qh_g, const __nv_bfloat16* __restrict__ ql_g,
    const __nv_bfloat16* __restrict__ kh_g, const __nv_bfloat16* __restrict__ kl_g,
    const __nv_bfloat16* __restrict__ vh_g, const __nv_bfloat16* __restrict__ vl_g,
    float* __restrict__ o, const float* __restrict__ dwp)
{
    extern __shared__ char smem[];
    const unsigned su = smem_to_u32(smem);
    float* Ot = (float*)(smem + OFF_KV);              // post-loop staging (buf0)
    float* Of = (float*)(smem + OFF_KV + KV_BUF);     // post-loop combine (buf1)

    const int tid = threadIdx.x;
    const int wid = tid >> 5, L = tid & 31;
    const int fr = L >> 2;           // 0..7
    const int lm = L >> 3, lr = L & 7;
    const int qt = blockIdx.x, hd = blockIdx.y, b = blockIdx.z;
    const int q0 = qt * BQ;
    const int bidx = wid >> 2;       // branch
    const int ws = wid & 3;          // warp slot -> q rows ms..ms+15 within strip
    const int ms = ws * 16;
    const int fc2 = (L & 3) * 2;

    const unsigned offA272 = (unsigned)((lr + ((lm & 1) << 3)) * QB + ((lm >> 1) << 4));
    const unsigned offB272 = (unsigned)((lr + ((lm >> 1) << 3)) * QB + ((lm & 1) << 4));

    const size_t rowbase = (size_t)b * SLEN;

    // ---- load Q tile (hi/lo), 128 x 128 bf16 each ----
#pragma unroll
    for (int i = 0; i < 8; i++) {
        int f = tid + i * 256;               // 0..2047
        int r = f >> 4, c = f & 15;
        size_t src = (rowbase + q0 + r) * EDIM + hd * 128 + c * 8;
        *(uint4*)(smem + OFF_QHI + r * QB + c * 16) = *(const uint4*)(qh_g + src);
        *(uint4*)(smem + OFF_QLO + r * QB + c * 16) = *(const uint4*)(ql_g + src);
    }

    float lA[2] = { 0.f, 0.f }, lB[2] = { 0.f, 0.f };
    float pacc[2][16][4];
#pragma unroll
    for (int s = 0; s < 2; s++)
#pragma unroll
        for (int nt = 0; nt < 16; nt++)
#pragma unroll
            for (int e = 0; e < 4; e++) pacc[s][nt][e] = 0.f;

    const int NT = SLEN / BKT;   // 32

    // issue tile 0 into buffer 0
    {
        const unsigned kvb = su + OFF_KV;
#pragma unroll
        for (int i = 0; i < 4; i++) {
            int f = tid + i * 256;
            int r = f >> 4, c = f & 15;
            size_t src = (rowbase + r) * EDIM + hd * 128 + c * 8;
            unsigned dsm = kvb + r * QB + c * 16;
            CP_ASYNC16(dsm + KV_KHI, kh_g + src);
            CP_ASYNC16(dsm + KV_KLO, kl_g + src);
            CP_ASYNC16(dsm + KV_VHI, vh_g + src);
            CP_ASYNC16(dsm + KV_VLO, vl_g + src);
        }
        CP_COMMIT();
    }

    for (int t = 0; t < NT; t++) {
        if (t > 0) __syncthreads();
        if (t + 1 < NT) {
            const unsigned kvb = su + OFF_KV + ((t + 1) & 1) * KV_BUF;
            const int kt1 = (t + 1) * BKT;
#pragma unroll
            for (int i = 0; i < 4; i++) {
                int f = tid + i * 256;
                int r = f >> 4, c = f & 15;
                size_t src = (rowbase + kt1 + r) * EDIM + hd * 128 + c * 8;
                unsigned dsm = kvb + r * QB + c * 16;
                CP_ASYNC16(dsm + KV_KHI, kh_g + src);
                CP_ASYNC16(dsm + KV_KLO, kl_g + src);
                CP_ASYNC16(dsm + KV_VHI, vh_g + src);
                CP_ASYNC16(dsm + KV_VLO, vl_g + src);
            }
            CP_COMMIT();
            CP_WAIT1();
        } else {
            CP_WAIT0();
        }
        __syncthreads();

        const unsigned kvb = su + OFF_KV + (t & 1) * KV_BUF;

        // ---- QK^T both strips, K frags loaded once, 4-chain interleave ----
        float s0[8][4], s1[8][4];
#pragma unroll
        for (int nt = 0; nt < 8; nt++)
#pragma unroll
            for (int e = 0; e < 4; e++) { s0[nt][e] = 0.f; s1[nt][e] = 0.f; }

#pragma unroll
        for (int ks = 0; ks < 4; ks++) {
            const unsigned kofb = (unsigned)(bidx * 128 + ks * 32);
            unsigned qh0[4], ql0[4], qh1[4], ql1[4];
            ldsm4(qh0, su + OFF_QHI + (ms) * QB + kofb + offA272);
            ldsm4(ql0, su + OFF_QLO + (ms) * QB + kofb + offA272);
            ldsm4(qh1, su + OFF_QHI + (64 + ms) * QB + kofb + offA272);
            ldsm4(ql1, su + OFF_QLO + (64 + ms) * QB + kofb + offA272);
#pragma unroll
            for (int ntp = 0; ntp < 4; ntp++) {
                unsigned th[4], tl[4];
                ldsm4(th, kvb + KV_KHI + (ntp * 16) * QB + kofb + offB272);
                ldsm4(tl, kvb + KV_KLO + (ntp * 16) * QB + kofb + offB272);
                // term 1: hi*hi across 4 independent chains
                mma16816(s0[2 * ntp],     qh0, th);
                mma16816(s0[2 * ntp + 1], qh0, th + 2);
                mma16816(s1[2 * ntp],     qh1, th);
                mma16816(s1[2 * ntp + 1], qh1, th + 2);
                // term 2: hi*lo
                mma16816(s0[2 * ntp],     qh0, tl);
                mma16816(s0[2 * ntp + 1], qh0, tl + 2);
                mma16816(s1[2 * ntp],     qh1, tl);
                mma16816(s1[2 * ntp + 1], qh1, tl + 2);
                // term 3: lo*hi
                mma16816(s0[2 * ntp],     ql0, th);
                mma16816(s0[2 * ntp + 1], ql0, th + 2);
                mma16816(s1[2 * ntp],     ql1, th);
                mma16816(s1[2 * ntp + 1], ql1, th + 2);
            }
        }

        // ---- no-max softmax: p = ex2(s) (log2e folded into q), partial sums ----
        {
            float suma = 0.f, sumb = 0.f;
#pragma unroll
            for (int nt = 0; nt < 8; nt++) {
                s0[nt][0] = ex2f(s0[nt][0]); suma += s0[nt][0];
                s0[nt][1] = ex2f(s0[nt][1]); suma += s0[nt][1];
                s0[nt][2] = ex2f(s0[nt][2]); sumb += s0[nt][2];
                s0[nt][3] = ex2f(s0[nt][3]); sumb += s0[nt][3];
            }
            lA[0] += suma; lB[0] += sumb;
            suma = 0.f; sumb = 0.f;
#pragma unroll
            for (int nt = 0; nt < 8; nt++) {
                s1[nt][0] = ex2f(s1[nt][0]); suma += s1[nt][0];
                s1[nt][1] = ex2f(s1[nt][1]); suma += s1[nt][1];
                s1[nt][2] = ex2f(s1[nt][2]); sumb += s1[nt][2];
                s1[nt][3] = ex2f(s1[nt][3]); sumb += s1[nt][3];
            }
            lA[1] += suma; lB[1] += sumb;
        }

        // ---- PV: per-ks P pack, V frags shared, 4-chain interleave ----
#pragma unroll
        for (int ks = 0; ks < 4; ks++) {
            unsigned Pf0h[4], Pf0l[4], Pf1h[4], Pf1l[4];
#pragma unroll
            for (int half = 0; half < 2; half++) {
                {
                    const float* sv = s0[2 * ks + half];
                    unsigned p01 = cvt2(sv[1], sv[0]);
                    unsigned p23 = cvt2(sv[3], sv[2]);
                    float r0 = sv[0] - __uint_as_float(p01 << 16);
                    float r1 = sv[1] - __uint_as_float(p01 & 0xFFFF0000u);
                    float r2 = sv[2] - __uint_as_float(p23 << 16);
                    float r3 = sv[3] - __uint_as_float(p23 & 0xFFFF0000u);
                    Pf0h[2 * half + 0] = p01;
                    Pf0h[2 * half + 1] = p23;
                    Pf0l[2 * half + 0] = cvt2(r1, r0);
                    Pf0l[2 * half + 1] = cvt2(r3, r2);
                }
                {
                    const float* sv = s1[2 * ks + half];
                    unsigned p01 = cvt2(sv[1], sv[0]);
                    unsigned p23 = cvt2(sv[3], sv[2]);
                    float r0 = sv[0] - __uint_as_float(p01 << 16);
                    float r1 = sv[1] - __uint_as_float(p01 & 0xFFFF0000u);
                    float r2 = sv[2] - __uint_as_float(p23 << 16);
                    float r3 = sv[3] - __uint_as_float(p23 & 0xFFFF0000u);
                    Pf1h[2 * half + 0] = p01;
                    Pf1h[2 * half + 1] = p23;
                    Pf1l[2 * half + 0] = cvt2(r1, r0);
                    Pf1l[2 * half + 1] = cvt2(r3, r2);
                }
            }
#pragma unroll
            for (int dtp = 0; dtp < 8; dtp++) {
                unsigned vh[4], vl[4];
                ldsm4t(vh, kvb + KV_VHI + (ks * 16) * QB + dtp * 32 + offA272);
                ldsm4t(vl, kvb + KV_VLO + (ks * 16) * QB + dtp * 32 + offA272);
                // term 1: Ph*Vh across 4 chains
                mma16816(pacc[0][2 * dtp],     Pf0h, vh);
                mma16816(pacc[0][2 * dtp + 1], Pf0h, vh + 2);
                mma16816(pacc[1][2 * dtp],     Pf1h, vh);
                mma16816(pacc[1][2 * dtp + 1], Pf1h, vh + 2);
                // term 2: Ph*Vl
                mma16816(pacc[0][2 * dtp],     Pf0h, vl);
                mma16816(pacc[0][2 * dtp + 1], Pf0h, vl + 2);
                mma16816(pacc[1][2 * dtp],     Pf1h, vl);
                mma16816(pacc[1][2 * dtp + 1], Pf1h, vl + 2);
                // term 3: Pl*Vh
                mma16816(pacc[0][2 * dtp],     Pf0l, vh);
                mma16816(pacc[0][2 * dtp + 1], Pf0l, vh + 2);
                mma16816(pacc[1][2 * dtp],     Pf1l, vh);
                mma16816(pacc[1][2 * dtp + 1], Pf1l, vh + 2);
            }
        }
    }
    __syncthreads();

    // ---- deferred l reduction across the 4 lanes sharing a row ----
#pragma unroll
    for (int s = 0; s < 2; s++) {
        lA[s] += __shfl_xor_sync(0xffffffffu, lA[s], 1);
        lA[s] += __shfl_xor_sync(0xffffffffu, lA[s], 2);
        lB[s] += __shfl_xor_sync(0xffffffffu, lB[s], 1);
        lB[s] += __shfl_xor_sync(0xffffffffu, lB[s], 2);
    }

    // ---- epilogue: o = O0/l0 - dw * O1/l1 ----
    const float dw = *dwp;
    if (bidx == 1) {
#pragma unroll
        for (int s = 0; s < 2; s++) {
            const float i0 = 1.f / lA[s], i1 = 1.f / lB[s];
            const int r0 = s * 64 + ms + fr;
#pragma unroll
            for (int nt = 0; nt < 16; nt++) {
                int d = nt * 8 + fc2;
                *(float2*)&Ot[r0 * OSR + d] =
                    make_float2(pacc[s][nt][0] * i0, pacc[s][nt][1] * i0);
                *(float2*)&Ot[(r0 + 8) * OSR + d] =
                    make_float2(pacc[s][nt][2] * i1, pacc[s][nt][3] * i1);
            }
        }
    }
    __syncthreads();
    if (bidx == 0) {
#pragma unroll
        for (int s = 0; s < 2; s++) {
            const float i0 = 1.f / lA[s], i1 = 1.f / lB[s];
            const int r0 = s * 64 + ms + fr;
#pragma unroll
            for (int nt = 0; nt < 16; nt++) {
                int d = nt * 8 + fc2;
                float2 t0 = *(float2*)&Ot[r0 * OSR + d];
                float2 t1 = *(float2*)&Ot[(r0 + 8) * OSR + d];
                *(float2*)&Of[r0 * OSR + d] =
                    make_float2(pacc[s][nt][0] * i0 - dw * t0.x,
                                pacc[s][nt][1] * i0 - dw * t0.y);
                *(float2*)&Of[(r0 + 8) * OSR + d] =
                    make_float2(pacc[s][nt][2] * i1 - dw * t1.x,
                                pacc[s][nt][3] * i1 - dw * t1.y);
            }
        }
    }
    __syncthreads();

    float* og = o + (rowbase + q0) * EDIM + hd * 128;
#pragma unroll
    for (int i = 0; i < 16; i++) {
        int f = tid + i * 256;
        int r = f >> 5, c4 = f & 31;
        *(float4*)(og + (size_t)r * EDIM + c4 * 4) = *(const float4*)&Of[r * OSR + c4 * 4];
    }
}

// ======================================================================
// RMSNorm over 1024-wide rows, fused split-bf16 output
// ======================================================================
__global__ void __launch_bounds__(256) rmsnorm_split_kernel(
    const float* __restrict__ x, const float* __restrict__ w,
    __nv_bfloat16* __restrict__ yhi, __nv_bfloat16* __restrict__ ylo)
{
    __shared__ float red[8];
    __shared__ float rtot;
    const int tid = threadIdx.x;
    const int row = blockIdx.x;
    const float* xr = x + (size_t)row * EDIM;

    float v[4];
    float s = 0.f;
#pragma unroll
    for (int j = 0; j < 4; j++) {
        v[j] = xr[tid + j * 256];
        s = fmaf(v[j], v[j], s);
    }
#pragma unroll
    for (int off = 16; off > 0; off >>= 1)
        s += __shfl_xor_sync(0xffffffffu, s, off);
    if ((tid & 31) == 0) red[tid >> 5] = s;
    __syncthreads();
    if (tid == 0) {
        float t = 0.f;
#pragma unroll
        for (int i = 0; i < 8; i++) t += red[i];
        rtot = rsqrtf(t * (1.0f / 1024.0f) + 1.1920929e-07f);
    }
    __syncthreads();
    float r = rtot;
#pragma unroll
    for (int j = 0; j < 4; j++) {
        int c = tid + j * 256;
        float f = v[j] * r * w[c];
        __nv_bfloat16 h = __float2bfloat16_rn(f);
        __nv_bfloat16 l = __float2bfloat16_rn(f - __bfloat162float(h));
        yhi[(size_t)row * EDIM + c] = h;
        ylo[(size_t)row * EDIM + c] = l;
    }
}

// ======================================================================
// launcher
// ======================================================================
extern "C" void kernel_launch(void* const* d_in, const int* in_sizes, int n_in,
                              void* d_out, int out_size)
{
    const float* x  = (const float*)d_in[0];
    const float* Wq = (const float*)d_in[1];
    const float* Wk = (const float*)d_in[2];
    const float* Wv = (const float*)d_in[3];
    const float* nw = (const float*)d_in[4];
    const float* Wo = (const float*)d_in[5];
    const float* bo = (const float*)d_in[6];
    const float* dw = (const float*)d_in[7];
    float* out = (float*)d_out;

    float* op;
    cudaGetSymbolAddress((void**)&op, g_o);
    __nv_bfloat16 *xh, *xl, *nh, *nl;
    cudaGetSymbolAddress((void**)&xh, g_xhi);
    cudaGetSymbolAddress((void**)&xl, g_xlo);
    cudaGetSymbolAddress((void**)&nh, g_nhi);
    cudaGetSymbolAddress((void**)&nl, g_nlo);
    __nv_bfloat16 *qh, *ql, *kh, *kl, *vh, *vl;
    cudaGetSymbolAddress((void**)&qh, g_qh);
    cudaGetSymbolAddress((void**)&ql, g_ql);
    cudaGetSymbolAddress((void**)&kh, g_kh);
    cudaGetSymbolAddress((void**)&kl, g_kl);
    cudaGetSymbolAddress((void**)&vh, g_vh);
    cudaGetSymbolAddress((void**)&vl, g_vl);
    __nv_bfloat16 *wqh, *wql, *wkh, *wkl, *wvh, *wvl, *woh, *wol;
    cudaGetSymbolAddress((void**)&wqh, g_wqhi);
    cudaGetSymbolAddress((void**)&wql, g_wqlo);
    cudaGetSymbolAddress((void**)&wkh, g_wkhi);
    cudaGetSymbolAddress((void**)&wkl, g_wklo);
    cudaGetSymbolAddress((void**)&wvh, g_wvhi);
    cudaGetSymbolAddress((void**)&wvl, g_wvlo);
    cudaGetSymbolAddress((void**)&woh, g_wohi);
    cudaGetSymbolAddress((void**)&wol, g_wolo);

    cudaFuncSetAttribute(diff_attn_mma_kernel,
                         cudaFuncAttributeMaxDynamicSharedMemorySize, ATT_SMEM_BYTES);
    cudaFuncSetAttribute(mma_gemm_kernel,
                         cudaFuncAttributeMaxDynamicSharedMemorySize, GSMEM_BYTES);

    // split conversions: x + fused 4-weight split
    const int xn4 = MROWS * EDIM / 4;
    const int wn4 = EDIM * EDIM / 4;
    split_bf16_kernel<<<xn4 / 256, 256>>>(x, xh, xl, xn4);
    SplitPtrs sp;
    sp.src[0] = Wq; sp.hi[0] = wqh; sp.lo[0] = wql;
    sp.src[1] = Wk; sp.hi[1] = wkh; sp.lo[1] = wkl;
    sp.src[2] = Wv; sp.hi[2] = wvh; sp.lo[2] = wvl;
    sp.src[3] = Wo; sp.hi[3] = woh; sp.lo[3] = wol;
    dim3 gs(wn4 / 256, 4);
    split_bf16_multi_kernel<<<gs, 256>>>(sp, wn4);

    // fused QKV projections; q pre-scaled by 0.125*log2e (p = ex2(s))
    QKVPtrs pq;
    pq.Bh[0] = wqh; pq.Bl[0] = wql; pq.Ch[0] = qh; pq.Cl[0] = ql;
    pq.cscale[0] = 0.125f * 1.4426950408889634f;
    pq.Bh[1] = wkh; pq.Bl[1] = wkl; pq.Ch[1] = kh; pq.Cl[1] = kl; pq.cscale[1] = 1.0f;
    pq.Bh[2] = wvh; pq.Bl[2] = wvl; pq.Ch[2] = vh; pq.Cl[2] = vl; pq.cscale[2] = 1.0f;
    dim3 gq(24, MROWS / 128);
    mma_gemm_kernel<<<gq, 256, GSMEM_BYTES>>>(xh, xl, pq, nullptr, nullptr, nullptr);

    // attention (HMMA, BQ=128, no-max ex2 softmax, double-buffered K/V)
    dim3 ga(SLEN / BQ, NHEAD, 2);
    diff_attn_mma_kernel<<<ga, 256, ATT_SMEM_BYTES>>>(qh, ql, kh, kl, vh, vl, op, dw);

    // rmsnorm + split
    rmsnorm_split_kernel<<<MROWS, 256>>>(op, nw, nh, nl);

    // output projection with bias + (1-dw) scale
    QKVPtrs po;
    po.Bh[0] = woh; po.Bl[0] = wol; po.Ch[0] = nullptr; po.Cl[0] = nullptr; po.cscale[0] = 1.0f;
    po.Bh[1] = woh; po.Bl[1] = wol; po.Ch[1] = nullptr; po.Cl[1] = nullptr; po.cscale[1] = 1.0f;
    po.Bh[2] = woh; po.Bl[2] = wol; po.Ch[2] = nullptr; po.Cl[2] = nullptr; po.cscale[2] = 1.0f;
    dim3 go(8, MROWS / 128);
    mma_gemm_kernel<<<go, 256, GSMEM_BYTES>>>(nh, nl, po, out, bo, dw);
}

// round 17
// speedup vs baseline: 1.0037x; 1.0037x over previous
#include <cuda_runtime.h>
#include <cuda_bf16.h>
#include <cstdint>
#include <cstddef>
#include <math.h>

#define MROWS 4096           // B*S
#define EDIM  1024
#define SLEN  2048
#define NHEAD 8

// ---------------- warp-level bf16 MMA (m16n8k16, fp32 accum) ----------------
__device__ __forceinline__ void mma16816(
    float* c, const unsigned* a, const unsigned* b)
{
    asm volatile(
        "mma.sync.aligned.m16n8k16.row.col.f32.bf16.bf16.f32 "
        "{%0,%1,%2,%3}, {%4,%5,%6,%7}, {%8,%9}, {%0,%1,%2,%3};"
        : "+f"(c[0]), "+f"(c[1]), "+f"(c[2]), "+f"(c[3])
        : "r"(a[0]), "r"(a[1]), "r"(a[2]), "r"(a[3]), "r"(b[0]), "r"(b[1]));
}
__device__ __forceinline__ void ldsm4(unsigned* r, unsigned addr) {
    asm volatile("ldmatrix.sync.aligned.m8n8.x4.shared.b16 {%0,%1,%2,%3}, [%4];"
        : "=r"(r[0]), "=r"(r[1]), "=r"(r[2]), "=r"(r[3]) : "r"(addr));
}
__device__ __forceinline__ void ldsm4t(unsigned* r, unsigned addr) {
    asm volatile("ldmatrix.sync.aligned.m8n8.x4.trans.shared.b16 {%0,%1,%2,%3}, [%4];"
        : "=r"(r[0]), "=r"(r[1]), "=r"(r[2]), "=r"(r[3]) : "r"(addr));
}
__device__ __forceinline__ unsigned smem_to_u32(const void* p) {
    unsigned a;
    asm("{ .reg .u64 t; cvta.to.shared.u64 t, %1; cvt.u32.u64 %0, t; }" : "=r"(a) : "l"(p));
    return a;
}
// pack two fp32 into bf16x2: low half = lo, high half = hi
__device__ __forceinline__ unsigned cvt2(float hi, float lo) {
    unsigned r; asm("cvt.rn.bf16x2.f32 %0, %1, %2;" : "=r"(r) : "f"(hi), "f"(lo));
    return r;
}
__device__ __forceinline__ float ex2f(float x) {
    float r; asm("ex2.approx.f32 %0, %1;" : "=f"(r) : "f"(x)); return r;
}
#define CP_ASYNC16(dst_u32, src) \
    asm volatile("cp.async.cg.shared.global [%0], [%1], 16;" :: "r"(dst_u32), "l"(src))
#define CP_COMMIT() asm volatile("cp.async.commit_group;" ::: "memory")
#define CP_WAIT0()  asm volatile("cp.async.wait_group 0;" ::: "memory")
#define CP_WAIT1()  asm volatile("cp.async.wait_group 1;" ::: "memory")

// ---------------- scratch (device globals: allocation-free) ----------------
__device__ float g_o[(size_t)MROWS * EDIM];
__device__ __nv_bfloat16 g_xhi[(size_t)MROWS * EDIM];
__device__ __nv_bfloat16 g_xlo[(size_t)MROWS * EDIM];
__device__ __nv_bfloat16 g_nhi[(size_t)MROWS * EDIM];
__device__ __nv_bfloat16 g_nlo[(size_t)MROWS * EDIM];
__device__ __nv_bfloat16 g_qh[(size_t)MROWS * EDIM];
__device__ __nv_bfloat16 g_ql[(size_t)MROWS * EDIM];
__device__ __nv_bfloat16 g_kh[(size_t)MROWS * EDIM];
__device__ __nv_bfloat16 g_kl[(size_t)MROWS * EDIM];
__device__ __nv_bfloat16 g_vh[(size_t)MROWS * EDIM];
__device__ __nv_bfloat16 g_vl[(size_t)MROWS * EDIM];
__device__ __nv_bfloat16 g_wqhi[(size_t)EDIM * EDIM];
__device__ __nv_bfloat16 g_wqlo[(size_t)EDIM * EDIM];
__device__ __nv_bfloat16 g_wkhi[(size_t)EDIM * EDIM];
__device__ __nv_bfloat16 g_wklo[(size_t)EDIM * EDIM];
__device__ __nv_bfloat16 g_wvhi[(size_t)EDIM * EDIM];
__device__ __nv_bfloat16 g_wvlo[(size_t)EDIM * EDIM];
__device__ __nv_bfloat16 g_wohi[(size_t)EDIM * EDIM];
__device__ __nv_bfloat16 g_wolo[(size_t)EDIM * EDIM];

struct QKVPtrs {
    const __nv_bfloat16* Bh[3];
    const __nv_bfloat16* Bl[3];
    __nv_bfloat16* Ch[3];
    __nv_bfloat16* Cl[3];
    float cscale[3];
};
struct SplitPtrs {
    const float* src[4];
    __nv_bfloat16* hi[4];
    __nv_bfloat16* lo[4];
};

// ======================================================================
// fp32 -> (bf16 hi, bf16 lo) split, vectorized float4
// ======================================================================
__global__ void __launch_bounds__(256) split_bf16_kernel(
    const float* __restrict__ x, __nv_bfloat16* __restrict__ hi,
    __nv_bfloat16* __restrict__ lo, int n4)
{
    int i = blockIdx.x * 256 + threadIdx.x;
    if (i >= n4) return;
    float4 v = ((const float4*)x)[i];
    float vv[4] = { v.x, v.y, v.z, v.w };
    __nv_bfloat16 h[4], l[4];
#pragma unroll
    for (int j = 0; j < 4; j++) {
        h[j] = __float2bfloat16_rn(vv[j]);
        l[j] = __float2bfloat16_rn(vv[j] - __bfloat162float(h[j]));
    }
    __nv_bfloat162* hp = (__nv_bfloat162*)hi;
    __nv_bfloat162* lp = (__nv_bfloat162*)lo;
    hp[i * 2 + 0] = __nv_bfloat162(h[0], h[1]);
    hp[i * 2 + 1] = __nv_bfloat162(h[2], h[3]);
    lp[i * 2 + 0] = __nv_bfloat162(l[0], l[1]);
    lp[i * 2 + 1] = __nv_bfloat162(l[2], l[3]);
}

// fused 4-weight split: blockIdx.y selects the weight matrix
__global__ void __launch_bounds__(256) split_bf16_multi_kernel(SplitPtrs p, int n4)
{
    int i = blockIdx.x * 256 + threadIdx.x;
    if (i >= n4) return;
    const int w = blockIdx.y;
    float4 v = ((const float4*)p.src[w])[i];
    float vv[4] = { v.x, v.y, v.z, v.w };
    __nv_bfloat16 h[4], l[4];
#pragma unroll
    for (int j = 0; j < 4; j++) {
        h[j] = __float2bfloat16_rn(vv[j]);
        l[j] = __float2bfloat16_rn(vv[j] - __bfloat162float(h[j]));
    }
    __nv_bfloat162* hp = (__nv_bfloat162*)p.hi[w];
    __nv_bfloat162* lp = (__nv_bfloat162*)p.lo[w];
    hp[i * 2 + 0] = __nv_bfloat162(h[0], h[1]);
    hp[i * 2 + 1] = __nv_bfloat162(h[2], h[3]);
    lp[i * 2 + 0] = __nv_bfloat162(l[0], l[1]);
    lp[i * 2 + 1] = __nv_bfloat162(l[2], l[3]);
}

// ======================================================================
// HMMA split-bf16 GEMM, BK=32, cp.async double-buffered, dynamic smem.
// ======================================================================
#define GTS   40                    // bf16 row stride (80 B)
#define GTILE (128 * GTS * 2)       // 10240 bytes per tile
#define GBUF  (4 * GTILE)           // 40960 bytes per buffer (Ah, Al, Bh, Bl)
#define GSMEM_BYTES (2 * GBUF)      // 81920

__global__ void __launch_bounds__(256, 2) mma_gemm_kernel(
    const __nv_bfloat16* __restrict__ Ahi, const __nv_bfloat16* __restrict__ Alo,
    QKVPtrs p, float* __restrict__ Cf,
    const float* __restrict__ bias, const float* __restrict__ dwp)
{
    extern __shared__ char gsm[];
    const unsigned su = smem_to_u32(gsm);

    const int tid = threadIdx.x;
    const int wid = tid >> 5, L = tid & 31;
    const int sel = blockIdx.x >> 3;
    const int bm = blockIdx.y * 128, bn = (blockIdx.x & 7) * 128;
    const int wm = (wid >> 2) * 64, wn = (wid & 3) * 32;
    const __nv_bfloat16* __restrict__ Bhi = p.Bh[sel];
    const __nv_bfloat16* __restrict__ Blo = p.Bl[sel];

    const int lrow = tid >> 1;                 // 0..127
    const int lcol = (tid & 1) * 16;           // bf16 offset within 32
    const unsigned soff = (unsigned)(lrow * 80 + (tid & 1) * 32);

    const int fr = L >> 2, fc = (L & 3) * 2;
    const int lm = L >> 3, lr = L & 7;
    const unsigned offA = (unsigned)((lr + ((lm & 1) << 3)) * 80 + ((lm >> 1) << 4));
    const unsigned offB = (unsigned)((lr + ((lm >> 1) << 3)) * 80 + ((lm & 1) << 4));

    float acc[4][4][4];
#pragma unroll
    for (int mt = 0; mt < 4; mt++)
#pragma unroll
        for (int nt = 0; nt < 4; nt++)
#pragma unroll
            for (int e = 0; e < 4; e++) acc[mt][nt][e] = 0.f;

    const int K = EDIM;
    const int nchunks = K / 32;   // 32

    {
        const unsigned base = su;
        const size_t arow = (size_t)(bm + lrow) * K + lcol;
        const size_t brow = (size_t)(bn + lrow) * K + lcol;
        CP_ASYNC16(base + 0 * GTILE + soff,      Ahi + arow);
        CP_ASYNC16(base + 0 * GTILE + soff + 16, Ahi + arow + 8);
        CP_ASYNC16(base + 1 * GTILE + soff,      Alo + arow);
        CP_ASYNC16(base + 1 * GTILE + soff + 16, Alo + arow + 8);
        CP_ASYNC16(base + 2 * GTILE + soff,      Bhi + brow);
        CP_ASYNC16(base + 2 * GTILE + soff + 16, Bhi + brow + 8);
        CP_ASYNC16(base + 3 * GTILE + soff,      Blo + brow);
        CP_ASYNC16(base + 3 * GTILE + soff + 16, Blo + brow + 8);
        CP_COMMIT();
    }

    for (int c = 0; c < nchunks; c++) {
        CP_WAIT0();
        __syncthreads();
        const unsigned base = su + (unsigned)((c & 1) * GBUF);
        if (c + 1 < nchunks) {
            const unsigned nbase = su + (unsigned)(((c + 1) & 1) * GBUF);
            const size_t arow = (size_t)(bm + lrow) * K + (c + 1) * 32 + lcol;
            const size_t brow = (size_t)(bn + lrow) * K + (c + 1) * 32 + lcol;
            CP_ASYNC16(nbase + 0 * GTILE + soff,      Ahi + arow);
            CP_ASYNC16(nbase + 0 * GTILE + soff + 16, Ahi + arow + 8);
            CP_ASYNC16(nbase + 1 * GTILE + soff,      Alo + arow);
            CP_ASYNC16(nbase + 1 * GTILE + soff + 16, Alo + arow + 8);
            CP_ASYNC16(nbase + 2 * GTILE + soff,      Bhi + brow);
            CP_ASYNC16(nbase + 2 * GTILE + soff + 16, Bhi + brow + 8);
            CP_ASYNC16(nbase + 3 * GTILE + soff,      Blo + brow);
            CP_ASYNC16(nbase + 3 * GTILE + soff + 16, Blo + brow + 8);
            CP_COMMIT();
        }

#pragma unroll
        for (int ks = 0; ks < 2; ks++) {
            const unsigned koff = (unsigned)(ks * 32);
            unsigned bh[4][2], bl[4][2];
#pragma unroll
            for (int ntp = 0; ntp < 2; ntp++) {
                unsigned t[4];
                ldsm4(t, base + 2 * GTILE + (wn + ntp * 16) * 80 + koff + offB);
                bh[2 * ntp][0] = t[0]; bh[2 * ntp][1] = t[1];
                bh[2 * ntp + 1][0] = t[2]; bh[2 * ntp + 1][1] = t[3];
                ldsm4(t, base + 3 * GTILE + (wn + ntp * 16) * 80 + koff + offB);
                bl[2 * ntp][0] = t[0]; bl[2 * ntp][1] = t[1];
                bl[2 * ntp + 1][0] = t[2]; bl[2 * ntp + 1][1] = t[3];
            }
#pragma unroll
            for (int mt = 0; mt < 4; mt++) {
                unsigned ah[4], al[4];
                ldsm4(ah, base + 0 * GTILE + (wm + mt * 16) * 80 + koff + offA);
                ldsm4(al, base + 1 * GTILE + (wm + mt * 16) * 80 + koff + offA);
#pragma unroll
                for (int nt = 0; nt < 4; nt++) mma16816(acc[mt][nt], ah, bh[nt]);
#pragma unroll
                for (int nt = 0; nt < 4; nt++) mma16816(acc[mt][nt], ah, bl[nt]);
#pragma unroll
                for (int nt = 0; nt < 4; nt++) mma16816(acc[mt][nt], al, bh[nt]);
            }
        }
    }

    if (Cf) {
        float sc = 1.0f;
        if (dwp) sc = 1.0f - *dwp;
#pragma unroll
        for (int mt = 0; mt < 4; mt++) {
#pragma unroll
            for (int nt = 0; nt < 4; nt++) {
                int row = bm + wm + mt * 16 + fr;
                int col = bn + wn + nt * 8 + fc;
                float b0 = 0.f, b1 = 0.f;
                if (bias) { b0 = bias[col]; b1 = bias[col + 1]; }
                float2 r0, r1;
                r0.x = (acc[mt][nt][0] + b0) * sc;
                r0.y = (acc[mt][nt][1] + b1) * sc;
                r1.x = (acc[mt][nt][2] + b0) * sc;
                r1.y = (acc[mt][nt][3] + b1) * sc;
                *(float2*)(Cf + (size_t)row * EDIM + col) = r0;
                *(float2*)(Cf + (size_t)(row + 8) * EDIM + col) = r1;
            }
        }
    } else {
        __nv_bfloat16* __restrict__ Chi = p.Ch[sel];
        __nv_bfloat16* __restrict__ Clo = p.Cl[sel];
        const float cs = p.cscale[sel];
#pragma unroll
        for (int mt = 0; mt < 4; mt++) {
#pragma unroll
            for (int nt = 0; nt < 4; nt++) {
                int row = bm + wm + mt * 16 + fr;
                int col = bn + wn + nt * 8 + fc;
#pragma unroll
                for (int half = 0; half < 2; half++) {
                    float v0 = acc[mt][nt][half * 2 + 0] * cs;
                    float v1 = acc[mt][nt][half * 2 + 1] * cs;
                    __nv_bfloat16 h0 = __float2bfloat16_rn(v0);
                    __nv_bfloat16 h1 = __float2bfloat16_rn(v1);
                    __nv_bfloat16 l0 = __float2bfloat16_rn(v0 - __bfloat162float(h0));
                    __nv_bfloat16 l1 = __float2bfloat16_rn(v1 - __bfloat162float(h1));
                    size_t off = (size_t)(row + half * 8) * EDIM + col;
                    *(__nv_bfloat162*)(Chi + off) = __nv_bfloat162(h0, h1);
                    *(__nv_bfloat162*)(Clo + off) = __nv_bfloat162(l0, l1);
                }
            }
        }
    }
}

// ======================================================================
// HMMA differential flash attention, BQ=128, no-max softmax (ex2) fused
// per ks-slice with PV so softmax(ks+1) MUFU overlaps PV(ks) MMA.
// q projection pre-scaled by 0.125*log2e, so p = ex2(s).
// CTA: (b, h, 128-q tile), 8 warps. Warps 0-3: branch0, 4-7: branch1.
// ======================================================================
#define BQ 128
#define BKT 64
#define QB  272   // byte stride for Q/K/V bf16 tiles (136 bf16)
#define OSR 132   // fp32 stride for O staging

#define OFF_QHI  0
#define OFF_QLO  34816
#define OFF_KV   69632       // 2 buffers x 4 tiles x 17408 bytes
#define KV_BUF   69632       // bytes per buffer set
#define KV_KHI   0
#define KV_KLO   17408
#define KV_VHI   34816
#define KV_VLO   52224
#define ATT_SMEM_BYTES (OFF_KV + 2 * KV_BUF)   // 208896

__global__ void __launch_bounds__(256) diff_attn_mma_kernel(
    const __nv_bfloat16* __restrict__ qh_g, const __nv_bfloat16* __restrict__ ql_g,
    const __nv_bfloat16* __restrict__ kh_g, const __nv_bfloat16* __restrict__ kl_g,
    const __nv_bfloat16* __restrict__ vh_g, const __nv_bfloat16* __restrict__ vl_g,
    float* __restrict__ o, const float* __restrict__ dwp)
{
    extern __shared__ char smem[];
    const unsigned su = smem_to_u32(smem);
    float* Ot = (float*)(smem + OFF_KV);              // post-loop staging (buf0)
    float* Of = (float*)(smem + OFF_KV + KV_BUF);     // post-loop combine (buf1)

    const int tid = threadIdx.x;
    const int wid = tid >> 5, L = tid & 31;
    const int fr = L >> 2;           // 0..7
    const int lm = L >> 3, lr = L & 7;
    const int qt = blockIdx.x, hd = blockIdx.y, b = blockIdx.z;
    const int q0 = qt * BQ;
    const int bidx = wid >> 2;       // branch
    const int ws = wid & 3;          // warp slot -> q rows ms..ms+15 within strip
    const int ms = ws * 16;
    const int fc2 = (L & 3) * 2;

    const unsigned offA272 = (unsigned)((lr + ((lm & 1) << 3)) * QB + ((lm >> 1) << 4));
    const unsigned offB272 = (unsigned)((lr + ((lm >> 1) << 3)) * QB + ((lm & 1) << 4));

    const size_t rowbase = (size_t)b * SLEN;

    // ---- load Q tile (hi/lo), 128 x 128 bf16 each ----
#pragma unroll
    for (int i = 0; i < 8; i++) {
        int f = tid + i * 256;               // 0..2047
        int r = f >> 4, c = f & 15;
        size_t src = (rowbase + q0 + r) * EDIM + hd * 128 + c * 8;
        *(uint4*)(smem + OFF_QHI + r * QB + c * 16) = *(const uint4*)(qh_g + src);
        *(uint4*)(smem + OFF_QLO + r * QB + c * 16) = *(const uint4*)(ql_g + src);
    }

    float lA[2] = { 0.f, 0.f }, lB[2] = { 0.f, 0.f };
    float pacc[2][16][4];
#pragma unroll
    for (int s = 0; s < 2; s++)
#pragma unroll
        for (int nt = 0; nt < 16; nt++)
#pragma unroll
            for (int e = 0; e < 4; e++) pacc[s][nt][e] = 0.f;

    const int NT = SLEN / BKT;   // 32

    // issue tile 0 into buffer 0
    {
        const unsigned kvb = su + OFF_KV;
#pragma unroll
        for (int i = 0; i < 4; i++) {
            int f = tid + i * 256;
            int r = f >> 4, c = f & 15;
            size_t src = (rowbase + r) * EDIM + hd * 128 + c * 8;
            unsigned dsm = kvb + r * QB + c * 16;
            CP_ASYNC16(dsm + KV_KHI, kh_g + src);
            CP_ASYNC16(dsm + KV_KLO, kl_g + src);
            CP_ASYNC16(dsm + KV_VHI, vh_g + src);
            CP_ASYNC16(dsm + KV_VLO, vl_g + src);
        }
        CP_COMMIT();
    }

    for (int t = 0; t < NT; t++) {
        if (t > 0) __syncthreads();
        if (t + 1 < NT) {
            const unsigned kvb = su + OFF_KV + ((t + 1) & 1) * KV_BUF;
            const int kt1 = (t + 1) * BKT;
#pragma unroll
            for (int i = 0; i < 4; i++) {
                int f = tid + i * 256;
                int r = f >> 4, c = f & 15;
                size_t src = (rowbase + kt1 + r) * EDIM + hd * 128 + c * 8;
                unsigned dsm = kvb + r * QB + c * 16;
                CP_ASYNC16(dsm + KV_KHI, kh_g + src);
                CP_ASYNC16(dsm + KV_KLO, kl_g + src);
                CP_ASYNC16(dsm + KV_VHI, vh_g + src);
                CP_ASYNC16(dsm + KV_VLO, vl_g + src);
            }
            CP_COMMIT();
            CP_WAIT1();
        } else {
            CP_WAIT0();
        }
        __syncthreads();

        const unsigned kvb = su + OFF_KV + (t & 1) * KV_BUF;

        // ---- QK^T both strips, K frags loaded once ----
        float s0[8][4], s1[8][4];
#pragma unroll
        for (int nt = 0; nt < 8; nt++)
#pragma unroll
            for (int e = 0; e < 4; e++) { s0[nt][e] = 0.f; s1[nt][e] = 0.f; }

#pragma unroll
        for (int ks = 0; ks < 4; ks++) {
            const unsigned kofb = (unsigned)(bidx * 128 + ks * 32);
            unsigned qh0[4], ql0[4], qh1[4], ql1[4];
            ldsm4(qh0, su + OFF_QHI + (ms) * QB + kofb + offA272);
            ldsm4(ql0, su + OFF_QLO + (ms) * QB + kofb + offA272);
            ldsm4(qh1, su + OFF_QHI + (64 + ms) * QB + kofb + offA272);
            ldsm4(ql1, su + OFF_QLO + (64 + ms) * QB + kofb + offA272);
#pragma unroll
            for (int ntp = 0; ntp < 4; ntp++) {
                unsigned th[4], tl[4];
                ldsm4(th, kvb + KV_KHI + (ntp * 16) * QB + kofb + offB272);
                ldsm4(tl, kvb + KV_KLO + (ntp * 16) * QB + kofb + offB272);
                mma16816(s0[2 * ntp],     qh0, th);
                mma16816(s0[2 * ntp + 1], qh0, th + 2);
                mma16816(s1[2 * ntp],     qh1, th);
                mma16816(s1[2 * ntp + 1], qh1, th + 2);
                mma16816(s0[2 * ntp],     qh0, tl);
                mma16816(s0[2 * ntp + 1], qh0, tl + 2);
                mma16816(s1[2 * ntp],     qh1, tl);
                mma16816(s1[2 * ntp + 1], qh1, tl + 2);
                mma16816(s0[2 * ntp],     ql0, th);
                mma16816(s0[2 * ntp + 1], ql0, th + 2);
                mma16816(s1[2 * ntp],     ql1, th);
                mma16816(s1[2 * ntp + 1], ql1, th + 2);
            }
        }

        // ---- fused softmax(ks) + PV(ks): MUFU of slice ks+1 overlaps PV MMA ----
#pragma unroll
        for (int ks = 0; ks < 4; ks++) {
            unsigned Pf0h[4], Pf0l[4], Pf1h[4], Pf1l[4];
            // softmax + pack for this 16-key slice (both strips)
#pragma unroll
            for (int half = 0; half < 2; half++) {
                {
                    float* sv = s0[2 * ks + half];
                    sv[0] = ex2f(sv[0]); sv[1] = ex2f(sv[1]);
                    sv[2] = ex2f(sv[2]); sv[3] = ex2f(sv[3]);
                    lA[0] += sv[0] + sv[1];
                    lB[0] += sv[2] + sv[3];
                    unsigned p01 = cvt2(sv[1], sv[0]);
                    unsigned p23 = cvt2(sv[3], sv[2]);
                    float r0 = sv[0] - __uint_as_float(p01 << 16);
                    float r1 = sv[1] - __uint_as_float(p01 & 0xFFFF0000u);
                    float r2 = sv[2] - __uint_as_float(p23 << 16);
                    float r3 = sv[3] - __uint_as_float(p23 & 0xFFFF0000u);
                    Pf0h[2 * half + 0] = p01;
                    Pf0h[2 * half + 1] = p23;
                    Pf0l[2 * half + 0] = cvt2(r1, r0);
                    Pf0l[2 * half + 1] = cvt2(r3, r2);
                }
                {
                    float* sv = s1[2 * ks + half];
                    sv[0] = ex2f(sv[0]); sv[1] = ex2f(sv[1]);
                    sv[2] = ex2f(sv[2]); sv[3] = ex2f(sv[3]);
                    lA[1] += sv[0] + sv[1];
                    lB[1] += sv[2] + sv[3];
                    unsigned p01 = cvt2(sv[1], sv[0]);
                    unsigned p23 = cvt2(sv[3], sv[2]);
                    float r0 = sv[0] - __uint_as_float(p01 << 16);
                    float r1 = sv[1] - __uint_as_float(p01 & 0xFFFF0000u);
                    float r2 = sv[2] - __uint_as_float(p23 << 16);
                    float r3 = sv[3] - __uint_as_float(p23 & 0xFFFF0000u);
                    Pf1h[2 * half + 0] = p01;
                    Pf1h[2 * half + 1] = p23;
                    Pf1l[2 * half + 0] = cvt2(r1, r0);
                    Pf1l[2 * half + 1] = cvt2(r3, r2);
                }
            }
            // PV for this slice (V frags shared across strips)
#pragma unroll
            for (int dtp = 0; dtp < 8; dtp++) {
                unsigned vh[4], vl[4];
                ldsm4t(vh, kvb + KV_VHI + (ks * 16) * QB + dtp * 32 + offA272);
                ldsm4t(vl, kvb + KV_VLO + (ks * 16) * QB + dtp * 32 + offA272);
                mma16816(pacc[0][2 * dtp],     Pf0h, vh);
                mma16816(pacc[0][2 * dtp + 1], Pf0h, vh + 2);
                mma16816(pacc[1][2 * dtp],     Pf1h, vh);
                mma16816(pacc[1][2 * dtp + 1], Pf1h, vh + 2);
                mma16816(pacc[0][2 * dtp],     Pf0h, vl);
                mma16816(pacc[0][2 * dtp + 1], Pf0h, vl + 2);
                mma16816(pacc[1][2 * dtp],     Pf1h, vl);
                mma16816(pacc[1][2 * dtp + 1], Pf1h, vl + 2);
                mma16816(pacc[0][2 * dtp],     Pf0l, vh);
                mma16816(pacc[0][2 * dtp + 1], Pf0l, vh + 2);
                mma16816(pacc[1][2 * dtp],     Pf1l, vh);
                mma16816(pacc[1][2 * dtp + 1], Pf1l, vh + 2);
            }
        }
    }
    __syncthreads();

    // ---- deferred l reduction across the 4 lanes sharing a row ----
#pragma unroll
    for (int s = 0; s < 2; s++) {
        lA[s] += __shfl_xor_sync(0xffffffffu, lA[s], 1);
        lA[s] += __shfl_xor_sync(0xffffffffu, lA[s], 2);
        lB[s] += __shfl_xor_sync(0xffffffffu, lB[s], 1);
        lB[s] += __shfl_xor_sync(0xffffffffu, lB[s], 2);
    }

    // ---- epilogue: o = O0/l0 - dw * O1/l1 ----
    const float dw = *dwp;
    if (bidx == 1) {
#pragma unroll
        for (int s = 0; s < 2; s++) {
            const float i0 = 1.f / lA[s], i1 = 1.f / lB[s];
            const int r0 = s * 64 + ms + fr;
#pragma unroll
            for (int nt = 0; nt < 16; nt++) {
                int d = nt * 8 + fc2;
                *(float2*)&Ot[r0 * OSR + d] =
                    make_float2(pacc[s][nt][0] * i0, pacc[s][nt][1] * i0);
                *(float2*)&Ot[(r0 + 8) * OSR + d] =
                    make_float2(pacc[s][nt][2] * i1, pacc[s][nt][3] * i1);
            }
        }
    }
    __syncthreads();
    if (bidx == 0) {
#pragma unroll
        for (int s = 0; s < 2; s++) {
            const float i0 = 1.f / lA[s], i1 = 1.f / lB[s];
            const int r0 = s * 64 + ms + fr;
#pragma unroll
            for (int nt = 0; nt < 16; nt++) {
                int d = nt * 8 + fc2;
                float2 t0 = *(float2*)&Ot[r0 * OSR + d];
                float2 t1 = *(float2*)&Ot[(r0 + 8) * OSR + d];
                *(float2*)&Of[r0 * OSR + d] =
                    make_float2(pacc[s][nt][0] * i0 - dw * t0.x,
                                pacc[s][nt][1] * i0 - dw * t0.y);
                *(float2*)&Of[(r0 + 8) * OSR + d] =
                    make_float2(pacc[s][nt][2] * i1 - dw * t1.x,
                                pacc[s][nt][3] * i1 - dw * t1.y);
            }
        }
    }
    __syncthreads();

    float* og = o + (rowbase + q0) * EDIM + hd * 128;
#pragma unroll
    for (int i = 0; i < 16; i++) {
        int f = tid + i * 256;
        int r = f >> 5, c4 = f & 31;
        *(float4*)(og + (size_t)r * EDIM + c4 * 4) = *(const float4*)&Of[r * OSR + c4 * 4];
    }
}

// ======================================================================
// RMSNorm over 1024-wide rows, fused split-bf16 output
// ======================================================================
__global__ void __launch_bounds__(256) rmsnorm_split_kernel(
    const float* __restrict__ x, const float* __restrict__ w,
    __nv_bfloat16* __restrict__ yhi, __nv_bfloat16* __restrict__ ylo)
{
    __shared__ float red[8];
    __shared__ float rtot;
    const int tid = threadIdx.x;
    const int row = blockIdx.x;
    const float* xr = x + (size_t)row * EDIM;

    float v[4];
    float s = 0.f;
#pragma unroll
    for (int j = 0; j < 4; j++) {
        v[j] = xr[tid + j * 256];
        s = fmaf(v[j], v[j], s);
    }
#pragma unroll
    for (int off = 16; off > 0; off >>= 1)
        s += __shfl_xor_sync(0xffffffffu, s, off);
    if ((tid & 31) == 0) red[tid >> 5] = s;
    __syncthreads();
    if (tid == 0) {
        float t = 0.f;
#pragma unroll
        for (int i = 0; i < 8; i++) t += red[i];
        rtot = rsqrtf(t * (1.0f / 1024.0f) + 1.1920929e-07f);
    }
    __syncthreads();
    float r = rtot;
#pragma unroll
    for (int j = 0; j < 4; j++) {
        int c = tid + j * 256;
        float f = v[j] * r * w[c];
        __nv_bfloat16 h = __float2bfloat16_rn(f);
        __nv_bfloat16 l = __float2bfloat16_rn(f - __bfloat162float(h));
        yhi[(size_t)row * EDIM + c] = h;
        ylo[(size_t)row * EDIM + c] = l;
    }
}

// ======================================================================
// launcher
// ======================================================================
extern "C" void kernel_launch(void* const* d_in, const int* in_sizes, int n_in,
                              void* d_out, int out_size)
{
    const float* x  = (const float*)d_in[0];
    const float* Wq = (const float*)d_in[1];
    const float* Wk = (const float*)d_in[2];
    const float* Wv = (const float*)d_in[3];
    const float* nw = (const float*)d_in[4];
    const float* Wo = (const float*)d_in[5];
    const float* bo = (const float*)d_in[6];
    const float* dw = (const float*)d_in[7];
    float* out = (float*)d_out;

    float* op;
    cudaGetSymbolAddress((void**)&op, g_o);
    __nv_bfloat16 *xh, *xl, *nh, *nl;
    cudaGetSymbolAddress((void**)&xh, g_xhi);
    cudaGetSymbolAddress((void**)&xl, g_xlo);
    cudaGetSymbolAddress((void**)&nh, g_nhi);
    cudaGetSymbolAddress((void**)&nl, g_nlo);
    __nv_bfloat16 *qh, *ql, *kh, *kl, *vh, *vl;
    cudaGetSymbolAddress((void**)&qh, g_qh);
    cudaGetSymbolAddress((void**)&ql, g_ql);
    cudaGetSymbolAddress((void**)&kh, g_kh);
    cudaGetSymbolAddress((void**)&kl, g_kl);
    cudaGetSymbolAddress((void**)&vh, g_vh);
    cudaGetSymbolAddress((void**)&vl, g_vl);
    __nv_bfloat16 *wqh, *wql, *wkh, *wkl, *wvh, *wvl, *woh, *wol;
    cudaGetSymbolAddress((void**)&wqh, g_wqhi);
    cudaGetSymbolAddress((void**)&wql, g_wqlo);
    cudaGetSymbolAddress((void**)&wkh, g_wkhi);
    cudaGetSymbolAddress((void**)&wkl, g_wklo);
    cudaGetSymbolAddress((void**)&wvh, g_wvhi);
    cudaGetSymbolAddress((void**)&wvl, g_wvlo);
    cudaGetSymbolAddress((void**)&woh, g_wohi);
    cudaGetSymbolAddress((void**)&wol, g_wolo);

    cudaFuncSetAttribute(diff_attn_mma_kernel,
                         cudaFuncAttributeMaxDynamicSharedMemorySize, ATT_SMEM_BYTES);
    cudaFuncSetAttribute(mma_gemm_kernel,
                         cudaFuncAttributeMaxDynamicSharedMemorySize, GSMEM_BYTES);

    // split conversions: x + fused 4-weight split
    const int xn4 = MROWS * EDIM / 4;
    const int wn4 = EDIM * EDIM / 4;
    split_bf16_kernel<<<xn4 / 256, 256>>>(x, xh, xl, xn4);
    SplitPtrs sp;
    sp.src[0] = Wq; sp.hi[0] = wqh; sp.lo[0] = wql;
    sp.src[1] = Wk; sp.hi[1] = wkh; sp.lo[1] = wkl;
    sp.src[2] = Wv; sp.hi[2] = wvh; sp.lo[2] = wvl;
    sp.src[3] = Wo; sp.hi[3] = woh; sp.lo[3] = wol;
    dim3 gs(wn4 / 256, 4);
    split_bf16_multi_kernel<<<gs, 256>>>(sp, wn4);

    // fused QKV projections; q pre-scaled by 0.125*log2e (p = ex2(s))
    QKVPtrs pq;
    pq.Bh[0] = wqh; pq.Bl[0] = wql; pq.Ch[0] = qh; pq.Cl[0] = ql;
    pq.cscale[0] = 0.125f * 1.4426950408889634f;
    pq.Bh[1] = wkh; pq.Bl[1] = wkl; pq.Ch[1] = kh; pq.Cl[1] = kl; pq.cscale[1] = 1.0f;
    pq.Bh[2] = wvh; pq.Bl[2] = wvl; pq.Ch[2] = vh; pq.Cl[2] = vl; pq.cscale[2] = 1.0f;
    dim3 gq(24, MROWS / 128);
    mma_gemm_kernel<<<gq, 256, GSMEM_BYTES>>>(xh, xl, pq, nullptr, nullptr, nullptr);

    // attention (HMMA, BQ=128, fused per-slice softmax+PV, double-buffered K/V)
    dim3 ga(SLEN / BQ, NHEAD, 2);
    diff_attn_mma_kernel<<<ga, 256, ATT_SMEM_BYTES>>>(qh, ql, kh, kl, vh, vl, op, dw);

    // rmsnorm + split
    rmsnorm_split_kernel<<<MROWS, 256>>>(op, nw, nh, nl);

    // output projection with bias + (1-dw) scale
    QKVPtrs po;
    po.Bh[0] = woh; po.Bl[0] = wol; po.Ch[0] = nullptr; po.Cl[0] = nullptr; po.cscale[0] = 1.0f;
    po.Bh[1] = woh; po.Bl[1] = wol; po.Ch[1] = nullptr; po.Cl[1] = nullptr; po.cscale[1] = 1.0f;
    po.Bh[2] = woh; po.Bl[2] = wol; po.Ch[2] = nullptr; po.Cl[2] = nullptr; po.cscale[2] = 1.0f;
    dim3 go(8, MROWS / 128);
    mma_gemm_kernel<<<go, 256, GSMEM_BYTES>>>(nh, nl, po, out, bo, dw);
}